// round 13
// baseline (speedup 1.0000x reference)
#include <cuda_runtime.h>
#include <math.h>
#include <stdint.h>

#define DT 512
#define DB 256
#define DI 256
#define DH 256
#define DG 768
#define DP (DT * DB)

typedef unsigned long long u64;

// ---------------- device scratch ----------
__device__ int      g_src[DP];
__device__ int      g_order[DP];
__device__ int      g_len[DB];
__device__ int      g_maxlen;
__device__ int      g_ntrue;
__device__ unsigned g_barg[16 * 32];   // 16 phase counters, 128B apart
__device__ float    g_h0[DB * DH];
__device__ float    g_h1[DB * DH];
__device__ float    g_gi[(size_t)DP * DG];

// ---------------- f32x2 helpers ----------
__device__ __forceinline__ u64 pack2(float lo, float hi) {
    u64 r; asm("mov.b64 %0, {%1, %2};" : "=l"(r) : "f"(lo), "f"(hi)); return r;
}
__device__ __forceinline__ void unpack2(u64 v, float& lo, float& hi) {
    asm("mov.b64 {%0, %1}, %2;" : "=f"(lo), "=f"(hi) : "l"(v));
}
__device__ __forceinline__ void fma2(u64& d, u64 a, u64 b) {
    asm("fma.rn.f32x2 %0, %1, %2, %0;" : "+l"(d) : "l"(a), "l"(b));
}
__device__ __forceinline__ u64 add2(u64 a, u64 b) {
    u64 r; asm("add.rn.f32x2 %0, %1, %2;" : "=l"(r) : "l"(a), "l"(b)); return r;
}
__device__ __forceinline__ float tanh_ap(float x) {
    float r; asm("tanh.approx.f32 %0, %1;" : "=f"(r) : "f"(x)); return r;
}

// ---------------------------------------------------------------------------
// Kernel 1: lengths, packed mask, ranks, order[], src[]  (1 CTA, 1024 thr)
// ---------------------------------------------------------------------------
__global__ void k_prep(const int* __restrict__ mask) {
    __shared__ int sLen[DB];
    __shared__ int sWm[32], sWp[32];
    __shared__ int sMax;
    const int tid = threadIdx.x;
    if (tid < 512) g_barg[tid] = 0u;
    if (tid < DB) sLen[tid] = 0;
    if (tid == 0) sMax = 0;
    __syncthreads();
    {
        const int b = tid & 255;
        int acc = 0;
        for (int t = tid >> 8; t < DT; t += 4) acc += (mask[(t << 8) + b] != 0) ? 1 : 0;
        atomicAdd(&sLen[b], acc);
    }
    __syncthreads();
    if (tid < DB) { g_len[tid] = sLen[tid]; atomicMax(&sMax, sLen[tid]); }
    __syncthreads();
    if (tid == 0) g_maxlen = sMax;

    const int base = tid << 7;
    int cm = 0, cp = 0;
    #pragma unroll 4
    for (int i = 0; i < 128; i++) {
        const int p = base + i;
        cm += (mask[p] != 0) ? 1 : 0;
        cp += ((p >> 8) < sLen[p & 255]) ? 1 : 0;
    }
    const int lane = tid & 31, wid = tid >> 5;
    int im = cm, ip = cp;
    #pragma unroll
    for (int d = 1; d < 32; d <<= 1) {
        const int um = __shfl_up_sync(0xffffffffu, im, d);
        const int up = __shfl_up_sync(0xffffffffu, ip, d);
        if (lane >= d) { im += um; ip += up; }
    }
    if (lane == 31) { sWm[wid] = im; sWp[wid] = ip; }
    __syncthreads();
    if (wid == 0) {
        const int am = sWm[lane], ap = sWp[lane];
        int jm = am, jp = ap;
        #pragma unroll
        for (int d = 1; d < 32; d <<= 1) {
            const int um = __shfl_up_sync(0xffffffffu, jm, d);
            const int up = __shfl_up_sync(0xffffffffu, jp, d);
            if (lane >= d) { jm += um; jp += up; }
        }
        sWm[lane] = jm - am;
        sWp[lane] = jp - ap;
        if (lane == 31) g_ntrue = jm;
    }
    __syncthreads();

    int mrank = sWm[wid] + im - cm;
    int prank = sWp[wid] + ip - cp;
    for (int i = 0; i < 128; i++) {
        const int p  = base + i;
        const int mt = (mask[p] != 0) ? 1 : 0;
        const int pt = ((p >> 8) < sLen[p & 255]) ? 1 : 0;
        if (mt) g_order[mrank] = p;
        g_src[p] = pt ? prank : -1;
        mrank += mt; prank += pt;
    }
    __syncthreads();
    for (int i = 0; i < 128; i++) {
        const int p = base + i;
        const int k = g_src[p];
        if (k >= 0) g_src[p] = g_order[k];
    }
}

// ---------------------------------------------------------------------------
// Kernel 2: gi = gather(x) @ W_ih^T + b_ih.
// 128x128 tile, 256 threads, 8x8 register tile (f32x2), XOR-16 swizzle.
// ---------------------------------------------------------------------------
#define GROW 132

__global__ void __launch_bounds__(256, 2)
k_gi(const float* __restrict__ x,
     const float* __restrict__ Wih,
     const float* __restrict__ bih) {
    __shared__ float As[16 * GROW];
    __shared__ float Bs[16 * GROW];
    __shared__ int   sSrc[128];
    __shared__ int   sAny;
    const int tid = threadIdx.x;
    const int gt = blockIdx.x;
    const int pt = blockIdx.y;

    if (tid == 0) sAny = 0;
    __syncthreads();
    if (tid < 128) {
        const int s = g_src[(pt << 7) + tid];
        sSrc[tid] = (s >= 0) ? s : 0;
        if (s >= 0) sAny = 1;
    }
    __syncthreads();
    if (!sAny) return;

    const int tx = tid & 15, ty = tid >> 4;
    const int m0 = ty << 3;
    const int n0 = tx << 2;

    const int fm = tid >> 1;
    const int fk = (tid & 1) << 3;
    const int fc = fm ^ (fk << 1);
    const float* xrow = x   + ((size_t)sSrc[fm] << 8);
    const float* wrow = Wih + ((size_t)((gt << 7) + fm) << 8);

    u64 acc[8][4];
    #pragma unroll
    for (int m = 0; m < 8; m++)
        #pragma unroll
        for (int n = 0; n < 4; n++) acc[m][n] = 0ull;

    for (int k0 = 0; k0 < DI; k0 += 16) {
        const float4 av0 = *(const float4*)(xrow + k0 + fk);
        const float4 av1 = *(const float4*)(xrow + k0 + fk + 4);
        const float4 bv0 = *(const float4*)(wrow + k0 + fk);
        const float4 bv1 = *(const float4*)(wrow + k0 + fk + 4);
        __syncthreads();
        As[(fk + 0) * GROW + fc] = av0.x; As[(fk + 1) * GROW + fc] = av0.y;
        As[(fk + 2) * GROW + fc] = av0.z; As[(fk + 3) * GROW + fc] = av0.w;
        As[(fk + 4) * GROW + fc] = av1.x; As[(fk + 5) * GROW + fc] = av1.y;
        As[(fk + 6) * GROW + fc] = av1.z; As[(fk + 7) * GROW + fc] = av1.w;
        Bs[(fk + 0) * GROW + fc] = bv0.x; Bs[(fk + 1) * GROW + fc] = bv0.y;
        Bs[(fk + 2) * GROW + fc] = bv0.z; Bs[(fk + 3) * GROW + fc] = bv0.w;
        Bs[(fk + 4) * GROW + fc] = bv1.x; Bs[(fk + 5) * GROW + fc] = bv1.y;
        Bs[(fk + 6) * GROW + fc] = bv1.z; Bs[(fk + 7) * GROW + fc] = bv1.w;
        __syncthreads();

        #pragma unroll
        for (int k = 0; k < 16; k++) {
            const int xr = (k & 8) << 1;
            const float* ar = As + k * GROW + (m0 ^ xr);
            const float* br = Bs + k * GROW;
            const int cn = n0 ^ xr;
            const float4  a0  = *(const float4*)(ar);
            const float4  a1  = *(const float4*)(ar + 4);
            const double2 bL  = *(const double2*)(br + cn);
            const double2 bH  = *(const double2*)(br + 64 + cn);
            const u64 bl0 = __double_as_longlong(bL.x);
            const u64 bl1 = __double_as_longlong(bL.y);
            const u64 bh0 = __double_as_longlong(bH.x);
            const u64 bh1 = __double_as_longlong(bH.y);
            const float am[8] = {a0.x, a0.y, a0.z, a0.w, a1.x, a1.y, a1.z, a1.w};
            #pragma unroll
            for (int m = 0; m < 8; m++) {
                const u64 p = pack2(am[m], am[m]);
                fma2(acc[m][0], p, bl0);
                fma2(acc[m][1], p, bl1);
                fma2(acc[m][2], p, bh0);
                fma2(acc[m][3], p, bh1);
            }
        }
    }

    const float4 biasA = *(const float4*)(bih + (gt << 7) + n0);
    const float4 biasB = *(const float4*)(bih + (gt << 7) + 64 + n0);
    #pragma unroll
    for (int m = 0; m < 8; m++) {
        const int row = (pt << 7) + m0 + m;
        float4 vA, vB;
        unpack2(acc[m][0], vA.x, vA.y);
        unpack2(acc[m][1], vA.z, vA.w);
        unpack2(acc[m][2], vB.x, vB.y);
        unpack2(acc[m][3], vB.z, vB.w);
        vA.x += biasA.x; vA.y += biasA.y; vA.z += biasA.z; vA.w += biasA.w;
        vB.x += biasB.x; vB.y += biasB.y; vB.z += biasB.z; vB.w += biasB.w;
        float* orow = g_gi + (size_t)row * DG + (gt << 7);
        *(float4*)(orow + n0)      = vA;
        *(float4*)(orow + 64 + n0) = vB;
    }
}

// ---------------------------------------------------------------------------
// Kernel 3: PERSISTENT recurrence v6 = R9 datapath + 2-phase pipelined
// barriers. 128 CTAs (16 jt x 8 bt), 256 threads. Each step splits b 32 ->
// 2 halves with independent barriers; phase p's barrier propagation hides
// behind phase p^1's compute. Lane = (kh, bq): 2 lanes split K 128/128,
// combined with one shfl_xor(16). W rows get a 16B mid-pad so k-halves hit
// different bank groups.
// ---------------------------------------------------------------------------
#define WROWF 520                      // 256k x 2jl + 4-float mid pad + tail
#define WSF (24 * WROWF)               // 12480 floats
#define HSF (16 * 256)                 // 16 b rows x 256 k
#define STP_SMEMB ((WSF + HSF) * 4)    // 66304 B
#define NJT 16u

extern __shared__ float s_stp[];

__global__ void __launch_bounds__(256, 1)
k_recp(const float* __restrict__ Whh, const float* __restrict__ bhh,
       float* __restrict__ out, const size_t oe) {
    const int tid = threadIdx.x;
    const int jp = tid >> 5, lane = tid & 31;
    const int kh = lane >> 4, bq = lane & 15;
    const int jt = blockIdx.x & 15, bt = blockIdx.x >> 4;
    const int j0 = (jt << 4) + (jp << 1);

    float* Ws = s_stp;
    float* Hs = s_stp + WSF;

    // ---- W fill once: rows g*256 + jt*16 + jr; smem row (jpw*3+g), j-pair
    //      interleaved, k>=128 shifted +4 floats (16B) for bank-group split
    #pragma unroll
    for (int it = 0; it < 12; it++) {
        const int idx = tid + (it << 8);
        const int row = idx >> 6, f4 = idx & 63;
        const int g = row >> 4, jr = row & 15;
        const int jpw = jr >> 1, jl = jr & 1;
        const float4 v = *(const float4*)(Whh +
            ((size_t)((g << 8) + (jt << 4) + jr) << 8) + (f4 << 2));
        float* rb = Ws + (jpw * 3 + g) * WROWF + jl;
        #pragma unroll
        for (int e = 0; e < 4; e++) {
            const int k = (f4 << 2) + e;
            rb[(k << 1) + ((k >> 7) << 2)] = (&v.x)[e];
        }
    }

    // group lmax over this bt's 32 columns
    int lmax = 0;
    #pragma unroll 8
    for (int i = 0; i < 32; i++) lmax = max(lmax, g_len[(bt << 5) + i]);
    const int ntrue = g_ntrue;
    const float2 bh_r = __ldg((const float2*)(bhh + j0));
    const float2 bh_z = __ldg((const float2*)(bhh + 256 + j0));
    const float2 bh_n = __ldg((const float2*)(bhh + 512 + j0));

    const float* wrB = Ws + (jp * 3 + 0) * WROWF + kh * 260;
    const float* wzB = Ws + (jp * 3 + 1) * WROWF + kh * 260;
    const float* wnB = Ws + (jp * 3 + 2) * WROWF + kh * 260;
    const float* hrow = Hs + (bq << 8);
    const int hx7 = bq & 7;
    const int ub0 = kh << 5;
    const int blen01[2] = { g_len[(bt << 5) + bq], g_len[(bt << 5) + 16 + bq] };

    for (int t = 0; t < lmax; t++) {
        const float* __restrict__ hin  = (t & 1) ? g_h1 : g_h0;
        float* __restrict__       hout = (t & 1) ? g_h0 : g_h1;

        #pragma unroll
        for (int ph = 0; ph < 2; ph++) {
            unsigned* bar = &g_barg[((bt << 1) + ph) << 5];

            // wait: all jt CTAs finished step t-1 for this half
            if (tid == 0 && t > 0) {
                const unsigned tgt = NJT * (unsigned)t;
                unsigned v;
                do {
                    asm volatile("ld.acquire.gpu.global.u32 %0, [%1];"
                                 : "=r"(v) : "l"(bar));
                } while (v < tgt);
            }
            __syncthreads();

            const int bglob = (bt << 5) + (ph << 4) + bq;
            const int blen  = blen01[ph];
            const int valid = (t < blen) ? 1 : 0;
            const int nflat = (t << 8) + bglob;

            // scalar prefetch (kh0 lanes own the epilogue)
            float2 gi_r, gi_z, gi_n, hold;
            int dest = -1;
            if (kh == 0) {
                if (valid && nflat < ntrue) dest = __ldg(&g_order[nflat]);
                const float* gp = g_gi + (size_t)nflat * DG;
                gi_r = __ldg((const float2*)(gp + j0));
                gi_z = __ldg((const float2*)(gp + 256 + j0));
                gi_n = __ldg((const float2*)(gp + 512 + j0));
                hold = *(const float2*)(hin + ((size_t)bglob << 8) + j0);
            }

            // h half-tile -> smem (16 rows x 256, XOR swizzle by b&7)
            #pragma unroll
            for (int it = 0; it < 4; it++) {
                const int idx = tid + (it << 8);
                const int hb = idx >> 6, ub = idx & 63;
                const float4 v = *(const float4*)(hin +
                    ((size_t)((bt << 5) + (ph << 4) + hb) << 8) + (ub << 2));
                *(float4*)(Hs + (hb << 8) + ((ub ^ (hb & 7)) << 2)) = v;
            }
            __syncthreads();

            u64 ar = 0ull, az = 0ull, an = 0ull;
            #pragma unroll 8
            for (int ii = 0; ii < 32; ii++) {
                const int u = (ub0 + ii) ^ hx7;
                const float4 hv = *(const float4*)(hrow + (u << 2));
                const int o = ii << 3;
                const double2 r01 = *(const double2*)(wrB + o);
                const double2 r23 = *(const double2*)(wrB + o + 4);
                const double2 z01 = *(const double2*)(wzB + o);
                const double2 z23 = *(const double2*)(wzB + o + 4);
                const double2 n01 = *(const double2*)(wnB + o);
                const double2 n23 = *(const double2*)(wnB + o + 4);
                const u64 h0 = pack2(hv.x, hv.x), h1 = pack2(hv.y, hv.y);
                const u64 h2 = pack2(hv.z, hv.z), h3 = pack2(hv.w, hv.w);
                fma2(ar, h0, __double_as_longlong(r01.x));
                fma2(ar, h1, __double_as_longlong(r01.y));
                fma2(ar, h2, __double_as_longlong(r23.x));
                fma2(ar, h3, __double_as_longlong(r23.y));
                fma2(az, h0, __double_as_longlong(z01.x));
                fma2(az, h1, __double_as_longlong(z01.y));
                fma2(az, h2, __double_as_longlong(z23.x));
                fma2(az, h3, __double_as_longlong(z23.y));
                fma2(an, h0, __double_as_longlong(n01.x));
                fma2(an, h1, __double_as_longlong(n01.y));
                fma2(an, h2, __double_as_longlong(n23.x));
                fma2(an, h3, __double_as_longlong(n23.y));
            }

            // combine the two K-halves (lane L <-> L^16)
            ar = add2(ar, __shfl_xor_sync(0xffffffffu, ar, 16));
            az = add2(az, __shfl_xor_sync(0xffffffffu, az, 16));
            an = add2(an, __shfl_xor_sync(0xffffffffu, an, 16));

            float ghr0, ghr1, ghz0, ghz1, ghn0, ghn1;
            unpack2(ar, ghr0, ghr1);
            unpack2(az, ghz0, ghz1);
            unpack2(an, ghn0, ghn1);

            float hn0, hn1;
            {
                const float r0 = 1.f / (1.f + __expf(-(gi_r.x + ghr0 + bh_r.x)));
                const float z0 = 1.f / (1.f + __expf(-(gi_z.x + ghz0 + bh_z.x)));
                const float n0 = tanh_ap(gi_n.x + r0 * (ghn0 + bh_n.x));
                hn0 = (1.f - z0) * n0 + z0 * hold.x;
                const float r1 = 1.f / (1.f + __expf(-(gi_r.y + ghr1 + bh_r.y)));
                const float z1 = 1.f / (1.f + __expf(-(gi_z.y + ghz1 + bh_z.y)));
                const float n1 = tanh_ap(gi_n.y + r1 * (ghn1 + bh_n.y));
                hn1 = (1.f - z1) * n1 + z1 * hold.y;
            }
            if (!valid) { hn0 = hold.x; hn1 = hold.y; }

            if (kh == 0) {
                *(float2*)(hout + ((size_t)bglob << 8) + j0) = make_float2(hn0, hn1);
                if (dest >= 0) {
                    const size_t o = ((size_t)dest << 8) + j0;
                    if (o + 1 < oe) *(float2*)(out + o) = make_float2(hn0, hn1);
                }
            }

            __syncthreads();
            if (tid == 0) {
                asm volatile("red.release.gpu.global.add.u32 [%0], 1;"
                             :: "l"(bar) : "memory");
            }
        }
    }

    // final hidden state for this bt-slice (jt==0 CTA), after BOTH halves
    // of the last step have fully landed group-wide.
    if (jt == 0) {
        if (tid == 0 && lmax > 0) {
            const unsigned tgt = NJT * (unsigned)lmax;
            unsigned v;
            do {
                asm volatile("ld.acquire.gpu.global.u32 %0, [%1];"
                             : "=r"(v) : "l"(&g_barg[(bt << 1) << 5]));
            } while (v < tgt);
            do {
                asm volatile("ld.acquire.gpu.global.u32 %0, [%1];"
                             : "=r"(v) : "l"(&g_barg[((bt << 1) + 1) << 5]));
            } while (v < tgt);
        }
        __syncthreads();
        const float* hf = (lmax & 1) ? g_h1 : g_h0;
        const size_t obase = (size_t)DP << 8;
        for (int idx = tid; idx < 32 * 64; idx += 256) {
            const int hb = (bt << 5) + (idx >> 6);
            const int kq = (idx & 63) << 2;
            const size_t o = obase + ((size_t)hb << 8) + kq;
            const float4 v = *(const float4*)(hf + ((size_t)hb << 8) + kq);
            if (o + 3 < oe) *(float4*)(out + o) = v;
        }
    }
}

// ---------------------------------------------------------------------------
// Small helpers
// ---------------------------------------------------------------------------
__global__ void k_zero4(float4* __restrict__ out, const size_t n4) {
    size_t i = (size_t)blockIdx.x * blockDim.x + threadIdx.x;
    const size_t stride = (size_t)gridDim.x * blockDim.x;
    const float4 z = make_float4(0.f, 0.f, 0.f, 0.f);
    for (; i < n4; i += stride) out[i] = z;
}

__global__ void k_init(const float* __restrict__ hx) {
    const int i = blockIdx.x * blockDim.x + threadIdx.x;
    if (i < DB * DH) g_h0[i] = hx[i];
}

// ---------------------------------------------------------------------------
extern "C" void kernel_launch(void* const* d_in, const int* in_sizes, int n_in,
                              void* d_out, int out_size) {
    const float* x    = (const float*)d_in[0];
    const float* hx   = (const float*)d_in[1];
    const int*   mask = (const int*)  d_in[2];
    const float* Wih  = (const float*)d_in[3];
    const float* Whh  = (const float*)d_in[4];
    const float* bih  = (const float*)d_in[5];
    const float* bhh  = (const float*)d_in[6];
    float* out = (float*)d_out;
    const size_t oe = (size_t)out_size;

    static int s_attr_done = 0;
    if (!s_attr_done) {
        cudaFuncSetAttribute(k_recp, cudaFuncAttributeMaxDynamicSharedMemorySize,
                             STP_SMEMB);
        s_attr_done = 1;
    }

    k_prep<<<1, 1024>>>(mask);
    k_zero4<<<1024, 256>>>((float4*)out, oe >> 2);
    k_init<<<64, 1024>>>(hx);
    k_gi<<<dim3(6, 1024), 256>>>(x, Wih, bih);
    k_recp<<<128, 256, STP_SMEMB>>>(Whh, bhh, out, oe);
}

// round 14
// speedup vs baseline: 1.2370x; 1.2370x over previous
#include <cuda_runtime.h>
#include <math.h>
#include <stdint.h>

#define DT 512
#define DB 256
#define DI 256
#define DH 256
#define DG 768
#define DP (DT * DB)

typedef unsigned long long u64;

// ---------------- device scratch ----------
__device__ int      g_src[DP];
__device__ int      g_order[DP];
__device__ int      g_len[DB];
__device__ int      g_maxlen;
__device__ int      g_ntrue;
__device__ unsigned g_barg[16 * 32];   // 16 group counters, 128B apart
__device__ float    g_h0[DB * DH];
__device__ float    g_h1[DB * DH];
__device__ float    g_gi[(size_t)DP * DG];

// ---------------- f32x2 helpers ----------
__device__ __forceinline__ u64 pack2(float lo, float hi) {
    u64 r; asm("mov.b64 %0, {%1, %2};" : "=l"(r) : "f"(lo), "f"(hi)); return r;
}
__device__ __forceinline__ void unpack2(u64 v, float& lo, float& hi) {
    asm("mov.b64 {%0, %1}, %2;" : "=f"(lo), "=f"(hi) : "l"(v));
}
__device__ __forceinline__ void fma2(u64& d, u64 a, u64 b) {
    asm("fma.rn.f32x2 %0, %1, %2, %0;" : "+l"(d) : "l"(a), "l"(b));
}
__device__ __forceinline__ float tanh_ap(float x) {
    float r; asm("tanh.approx.f32 %0, %1;" : "=f"(r) : "f"(x)); return r;
}

// ---------------------------------------------------------------------------
// Kernel 1: lengths, packed mask, ranks, order[], src[]  (1 CTA, 1024 thr)
// ---------------------------------------------------------------------------
__global__ void k_prep(const int* __restrict__ mask) {
    __shared__ int sLen[DB];
    __shared__ int sWm[32], sWp[32];
    __shared__ int sMax;
    const int tid = threadIdx.x;
    if (tid < 512) g_barg[tid] = 0u;
    if (tid < DB) sLen[tid] = 0;
    if (tid == 0) sMax = 0;
    __syncthreads();
    {
        const int b = tid & 255;
        int acc = 0;
        for (int t = tid >> 8; t < DT; t += 4) acc += (mask[(t << 8) + b] != 0) ? 1 : 0;
        atomicAdd(&sLen[b], acc);
    }
    __syncthreads();
    if (tid < DB) { g_len[tid] = sLen[tid]; atomicMax(&sMax, sLen[tid]); }
    __syncthreads();
    if (tid == 0) g_maxlen = sMax;

    const int base = tid << 7;
    int cm = 0, cp = 0;
    #pragma unroll 4
    for (int i = 0; i < 128; i++) {
        const int p = base + i;
        cm += (mask[p] != 0) ? 1 : 0;
        cp += ((p >> 8) < sLen[p & 255]) ? 1 : 0;
    }
    const int lane = tid & 31, wid = tid >> 5;
    int im = cm, ip = cp;
    #pragma unroll
    for (int d = 1; d < 32; d <<= 1) {
        const int um = __shfl_up_sync(0xffffffffu, im, d);
        const int up = __shfl_up_sync(0xffffffffu, ip, d);
        if (lane >= d) { im += um; ip += up; }
    }
    if (lane == 31) { sWm[wid] = im; sWp[wid] = ip; }
    __syncthreads();
    if (wid == 0) {
        const int am = sWm[lane], ap = sWp[lane];
        int jm = am, jp = ap;
        #pragma unroll
        for (int d = 1; d < 32; d <<= 1) {
            const int um = __shfl_up_sync(0xffffffffu, jm, d);
            const int up = __shfl_up_sync(0xffffffffu, jp, d);
            if (lane >= d) { jm += um; jp += up; }
        }
        sWm[lane] = jm - am;
        sWp[lane] = jp - ap;
        if (lane == 31) g_ntrue = jm;
    }
    __syncthreads();

    int mrank = sWm[wid] + im - cm;
    int prank = sWp[wid] + ip - cp;
    for (int i = 0; i < 128; i++) {
        const int p  = base + i;
        const int mt = (mask[p] != 0) ? 1 : 0;
        const int pt = ((p >> 8) < sLen[p & 255]) ? 1 : 0;
        if (mt) g_order[mrank] = p;
        g_src[p] = pt ? prank : -1;
        mrank += mt; prank += pt;
    }
    __syncthreads();
    for (int i = 0; i < 128; i++) {
        const int p = base + i;
        const int k = g_src[p];
        if (k >= 0) g_src[p] = g_order[k];
    }
}

// ---------------------------------------------------------------------------
// Kernel 2: gi = gather(x) @ W_ih^T + b_ih.
// 128x128 tile, 256 threads, 8x8 register tile (f32x2), XOR-16 swizzle.
// (unchanged from the proven 528us version)
// ---------------------------------------------------------------------------
#define GROW 132

__global__ void __launch_bounds__(256, 2)
k_gi(const float* __restrict__ x,
     const float* __restrict__ Wih,
     const float* __restrict__ bih) {
    __shared__ float As[16 * GROW];
    __shared__ float Bs[16 * GROW];
    __shared__ int   sSrc[128];
    __shared__ int   sAny;
    const int tid = threadIdx.x;
    const int gt = blockIdx.x;
    const int pt = blockIdx.y;

    if (tid == 0) sAny = 0;
    __syncthreads();
    if (tid < 128) {
        const int s = g_src[(pt << 7) + tid];
        sSrc[tid] = (s >= 0) ? s : 0;
        if (s >= 0) sAny = 1;
    }
    __syncthreads();
    if (!sAny) return;

    const int tx = tid & 15, ty = tid >> 4;
    const int m0 = ty << 3;
    const int n0 = tx << 2;

    const int fm = tid >> 1;
    const int fk = (tid & 1) << 3;
    const int fc = fm ^ (fk << 1);
    const float* xrow = x   + ((size_t)sSrc[fm] << 8);
    const float* wrow = Wih + ((size_t)((gt << 7) + fm) << 8);

    u64 acc[8][4];
    #pragma unroll
    for (int m = 0; m < 8; m++)
        #pragma unroll
        for (int n = 0; n < 4; n++) acc[m][n] = 0ull;

    for (int k0 = 0; k0 < DI; k0 += 16) {
        const float4 av0 = *(const float4*)(xrow + k0 + fk);
        const float4 av1 = *(const float4*)(xrow + k0 + fk + 4);
        const float4 bv0 = *(const float4*)(wrow + k0 + fk);
        const float4 bv1 = *(const float4*)(wrow + k0 + fk + 4);
        __syncthreads();
        As[(fk + 0) * GROW + fc] = av0.x; As[(fk + 1) * GROW + fc] = av0.y;
        As[(fk + 2) * GROW + fc] = av0.z; As[(fk + 3) * GROW + fc] = av0.w;
        As[(fk + 4) * GROW + fc] = av1.x; As[(fk + 5) * GROW + fc] = av1.y;
        As[(fk + 6) * GROW + fc] = av1.z; As[(fk + 7) * GROW + fc] = av1.w;
        Bs[(fk + 0) * GROW + fc] = bv0.x; Bs[(fk + 1) * GROW + fc] = bv0.y;
        Bs[(fk + 2) * GROW + fc] = bv0.z; Bs[(fk + 3) * GROW + fc] = bv0.w;
        Bs[(fk + 4) * GROW + fc] = bv1.x; Bs[(fk + 5) * GROW + fc] = bv1.y;
        Bs[(fk + 6) * GROW + fc] = bv1.z; Bs[(fk + 7) * GROW + fc] = bv1.w;
        __syncthreads();

        #pragma unroll
        for (int k = 0; k < 16; k++) {
            const int xr = (k & 8) << 1;
            const float* ar = As + k * GROW + (m0 ^ xr);
            const float* br = Bs + k * GROW;
            const int cn = n0 ^ xr;
            const float4  a0  = *(const float4*)(ar);
            const float4  a1  = *(const float4*)(ar + 4);
            const double2 bL  = *(const double2*)(br + cn);
            const double2 bH  = *(const double2*)(br + 64 + cn);
            const u64 bl0 = __double_as_longlong(bL.x);
            const u64 bl1 = __double_as_longlong(bL.y);
            const u64 bh0 = __double_as_longlong(bH.x);
            const u64 bh1 = __double_as_longlong(bH.y);
            const float am[8] = {a0.x, a0.y, a0.z, a0.w, a1.x, a1.y, a1.z, a1.w};
            #pragma unroll
            for (int m = 0; m < 8; m++) {
                const u64 p = pack2(am[m], am[m]);
                fma2(acc[m][0], p, bl0);
                fma2(acc[m][1], p, bl1);
                fma2(acc[m][2], p, bh0);
                fma2(acc[m][3], p, bh1);
            }
        }
    }

    const float4 biasA = *(const float4*)(bih + (gt << 7) + n0);
    const float4 biasB = *(const float4*)(bih + (gt << 7) + 64 + n0);
    #pragma unroll
    for (int m = 0; m < 8; m++) {
        const int row = (pt << 7) + m0 + m;
        float4 vA, vB;
        unpack2(acc[m][0], vA.x, vA.y);
        unpack2(acc[m][1], vA.z, vA.w);
        unpack2(acc[m][2], vB.x, vB.y);
        unpack2(acc[m][3], vB.z, vB.w);
        vA.x += biasA.x; vA.y += biasA.y; vA.z += biasA.z; vA.w += biasA.w;
        vB.x += biasB.x; vB.y += biasB.y; vB.z += biasB.z; vB.w += biasB.w;
        float* orow = g_gi + (size_t)row * DG + (gt << 7);
        *(float4*)(orow + n0)      = vA;
        *(float4*)(orow + 64 + n0) = vB;
    }
}

// ---------------------------------------------------------------------------
// Kernel 3: PERSISTENT recurrence (R9 structure, EXACT datapath) + two
// latency-exposure fixes:
//   (a) `out` scatter store moved AFTER the barrier arrive, so its DRAM
//       drain overlaps the spin-wait instead of delaying the release.
//   (b) gi/dest for step t+1 prefetched after the arrive (no h dependency),
//       overlapping the spin-wait; consumed at step t+1's epilogue.
// 128 CTAs (16 jt x 8 bt), 256 threads, group barriers (16 arrivals).
// ---------------------------------------------------------------------------
#define WSF (24 * 520)                     // W floats: 24 rows x (512+8)
#define STP_SMEMF (WSF + 32 * 256)         // + h tile 32b x 256k
#define STP_SMEMB (STP_SMEMF * 4)          // 82688 B

extern __shared__ float s_stp[];

__global__ void __launch_bounds__(256, 1)
k_recp(const float* __restrict__ Whh, const float* __restrict__ bhh,
       float* __restrict__ out, const size_t oe) {
    const int tid = threadIdx.x;
    const int jp = tid >> 5, bl = tid & 31;
    const int jt = blockIdx.x & 15, bt = blockIdx.x >> 4;
    const int bglob = (bt << 5) + bl;
    const int j0 = (jt << 4) + (jp << 1);
    unsigned* bar = &g_barg[bt << 5];

    float* Ws = s_stp;
    float* Hs = s_stp + WSF;

    // ---- W tile -> smem ONCE, j-pair interleaved: Ws[(jp*3+g)*520 + k*2 + jl]
    #pragma unroll
    for (int it = 0; it < 12; it++) {
        const int idx = tid + (it << 8);
        const int row = idx >> 6, f4 = idx & 63;
        const int g = row >> 4, jr = row & 15;
        const int jpl = jr >> 1, jl = jr & 1;
        const float4 v = *(const float4*)(Whh +
            ((size_t)((g << 8) + (jt << 4) + jr) << 8) + (f4 << 2));
        float* rb = Ws + (jpl * 3 + g) * 520 + jl;
        rb[(((f4 << 2) + 0) << 1)] = v.x;
        rb[(((f4 << 2) + 1) << 1)] = v.y;
        rb[(((f4 << 2) + 2) << 1)] = v.z;
        rb[(((f4 << 2) + 3) << 1)] = v.w;
    }

    // loop-invariant scalars; group lmax over this bt's 32 columns
    int lmax = 0;
    #pragma unroll 8
    for (int i = 0; i < 32; i++) lmax = max(lmax, g_len[(bt << 5) + i]);
    const int ntrue = g_ntrue;
    const int blen  = g_len[bglob];
    const float2 bh_r = __ldg((const float2*)(bhh + j0));
    const float2 bh_z = __ldg((const float2*)(bhh + 256 + j0));
    const float2 bh_n = __ldg((const float2*)(bhh + 512 + j0));

    const float* wr = Ws + (jp * 3 + 0) * 520;
    const float* wz = Ws + (jp * 3 + 1) * 520;
    const float* wn = Ws + (jp * 3 + 2) * 520;
    const float* hrow = Hs + (bl << 8);
    const int hxor = bl & 7;

    // ---- gi/dest prefetch registers (step 0 loaded up front)
    float2 p_gr, p_gz, p_gn;
    int    p_dest;
    {
        const int nflat = bglob;                       // t = 0
        const int v0 = (0 < blen) ? 1 : 0;
        p_dest = (v0 && nflat < ntrue) ? __ldg(&g_order[nflat]) : -1;
        const float* gp = g_gi + (size_t)nflat * DG;
        p_gr = __ldg((const float2*)(gp + j0));
        p_gz = __ldg((const float2*)(gp + 256 + j0));
        p_gn = __ldg((const float2*)(gp + 512 + j0));
    }

    for (int t = 0; t < lmax; t++) {
        const float* __restrict__ hin  = (t & 1) ? g_h1 : g_h0;
        float* __restrict__       hout = (t & 1) ? g_h0 : g_h1;

        // consume prefetched scalars for this step
        const int    valid = (t < blen) ? 1 : 0;
        const int    dest  = p_dest;
        const float2 gi_r = p_gr, gi_z = p_gz, gi_n = p_gn;
        const float2 hold = *(const float2*)(hin + ((size_t)bglob << 8) + j0);

        // h tile -> smem, swizzled: unit u -> u ^ (b&7)
        #pragma unroll
        for (int it = 0; it < 8; it++) {
            const int idx = tid + (it << 8);
            const int b = idx >> 6, ub = idx & 63;
            const float4 v = *(const float4*)(hin + ((size_t)((bt << 5) + b) << 8) + (ub << 2));
            *(float4*)(Hs + (b << 8) + ((ub ^ (b & 7)) << 2)) = v;
        }
        __syncthreads();

        u64 ar = 0ull, az = 0ull, an = 0ull;
        #pragma unroll 8
        for (int i = 0; i < 64; i++) {
            const float4 hv = *(const float4*)(hrow + ((i ^ hxor) << 2));
            const int o = i << 3;
            const double2 r01 = *(const double2*)(wr + o);
            const double2 r23 = *(const double2*)(wr + o + 4);
            const double2 z01 = *(const double2*)(wz + o);
            const double2 z23 = *(const double2*)(wz + o + 4);
            const double2 n01 = *(const double2*)(wn + o);
            const double2 n23 = *(const double2*)(wn + o + 4);
            const u64 h0 = pack2(hv.x, hv.x), h1 = pack2(hv.y, hv.y);
            const u64 h2 = pack2(hv.z, hv.z), h3 = pack2(hv.w, hv.w);
            fma2(ar, h0, __double_as_longlong(r01.x));
            fma2(ar, h1, __double_as_longlong(r01.y));
            fma2(ar, h2, __double_as_longlong(r23.x));
            fma2(ar, h3, __double_as_longlong(r23.y));
            fma2(az, h0, __double_as_longlong(z01.x));
            fma2(az, h1, __double_as_longlong(z01.y));
            fma2(az, h2, __double_as_longlong(z23.x));
            fma2(az, h3, __double_as_longlong(z23.y));
            fma2(an, h0, __double_as_longlong(n01.x));
            fma2(an, h1, __double_as_longlong(n01.y));
            fma2(an, h2, __double_as_longlong(n23.x));
            fma2(an, h3, __double_as_longlong(n23.y));
        }

        float ghr0, ghr1, ghz0, ghz1, ghn0, ghn1;
        unpack2(ar, ghr0, ghr1);
        unpack2(az, ghz0, ghz1);
        unpack2(an, ghn0, ghn1);

        float hn0, hn1;
        {
            const float r0 = 1.f / (1.f + __expf(-(gi_r.x + ghr0 + bh_r.x)));
            const float z0 = 1.f / (1.f + __expf(-(gi_z.x + ghz0 + bh_z.x)));
            const float n0 = tanh_ap(gi_n.x + r0 * (ghn0 + bh_n.x));
            hn0 = (1.f - z0) * n0 + z0 * hold.x;
            const float r1 = 1.f / (1.f + __expf(-(gi_r.y + ghr1 + bh_r.y)));
            const float z1 = 1.f / (1.f + __expf(-(gi_z.y + ghz1 + bh_z.y)));
            const float n1 = tanh_ap(gi_n.y + r1 * (ghn1 + bh_n.y));
            hn1 = (1.f - z1) * n1 + z1 * hold.y;
        }
        if (!valid) { hn0 = hold.x; hn1 = hold.y; }

        // hout store MUST precede the release (peer CTAs read it next step)
        *(float2*)(hout + ((size_t)bglob << 8) + j0) = make_float2(hn0, hn1);

        __syncthreads();
        if (tid == 0) {
            asm volatile("red.release.gpu.global.add.u32 [%0], 1;"
                         :: "l"(bar) : "memory");
        }

        // ---- latency overlap window: these drain/load while we wait ----
        // (a) scattered out store (no in-kernel consumer; kernel-end fences)
        if (dest >= 0) {
            const size_t o = ((size_t)dest << 8) + j0;
            if (o + 1 < oe) *(float2*)(out + o) = make_float2(hn0, hn1);
        }
        // (b) prefetch gi/dest for step t+1 (depends only on t)
        if (t + 1 < lmax) {
            const int nflat = ((t + 1) << 8) + bglob;
            const int v1 = (t + 1 < blen) ? 1 : 0;
            p_dest = (v1 && nflat < ntrue) ? __ldg(&g_order[nflat]) : -1;
            const float* gp = g_gi + (size_t)nflat * DG;
            p_gr = __ldg((const float2*)(gp + j0));
            p_gz = __ldg((const float2*)(gp + 256 + j0));
            p_gn = __ldg((const float2*)(gp + 512 + j0));
        }

        if (tid == 0) {
            const unsigned tgt = 16u * (unsigned)(t + 1);
            unsigned v;
            do {
                asm volatile("ld.acquire.gpu.global.u32 %0, [%1];"
                             : "=r"(v) : "l"(bar));
            } while (v < tgt);
        }
        __syncthreads();
    }

    // final hidden state for this bt-slice (written by jt==0 CTA of the group)
    if (jt == 0) {
        const float* hf = (lmax & 1) ? g_h1 : g_h0;
        const size_t obase = (size_t)DP << 8;
        for (int idx = tid; idx < 32 * 64; idx += 256) {
            const int b  = (bt << 5) + (idx >> 6);
            const int kq = (idx & 63) << 2;
            const size_t o = obase + ((size_t)b << 8) + kq;
            const float4 v = *(const float4*)(hf + ((size_t)b << 8) + kq);
            if (o + 3 < oe) *(float4*)(out + o) = v;
        }
    }
}

// ---------------------------------------------------------------------------
// Small helpers
// ---------------------------------------------------------------------------
__global__ void k_zero4(float4* __restrict__ out, const size_t n4) {
    size_t i = (size_t)blockIdx.x * blockDim.x + threadIdx.x;
    const size_t stride = (size_t)gridDim.x * blockDim.x;
    const float4 z = make_float4(0.f, 0.f, 0.f, 0.f);
    for (; i < n4; i += stride) out[i] = z;
}

__global__ void k_init(const float* __restrict__ hx) {
    const int i = blockIdx.x * blockDim.x + threadIdx.x;
    if (i < DB * DH) g_h0[i] = hx[i];
}

// ---------------------------------------------------------------------------
extern "C" void kernel_launch(void* const* d_in, const int* in_sizes, int n_in,
                              void* d_out, int out_size) {
    const float* x    = (const float*)d_in[0];
    const float* hx   = (const float*)d_in[1];
    const int*   mask = (const int*)  d_in[2];
    const float* Wih  = (const float*)d_in[3];
    const float* Whh  = (const float*)d_in[4];
    const float* bih  = (const float*)d_in[5];
    const float* bhh  = (const float*)d_in[6];
    float* out = (float*)d_out;
    const size_t oe = (size_t)out_size;

    static int s_attr_done = 0;
    if (!s_attr_done) {
        cudaFuncSetAttribute(k_recp, cudaFuncAttributeMaxDynamicSharedMemorySize,
                             STP_SMEMB);
        s_attr_done = 1;
    }

    k_prep<<<1, 1024>>>(mask);
    k_zero4<<<1024, 256>>>((float4*)out, oe >> 2);
    k_init<<<64, 1024>>>(hx);
    k_gi<<<dim3(6, 1024), 256>>>(x, Wih, bih);
    k_recp<<<128, 256, STP_SMEMB>>>(Whh, bhh, out, oe);
}